// round 3
// baseline (speedup 1.0000x reference)
#include <cuda_runtime.h>
#include <math.h>
#include <stdint.h>

// ---------------- problem constants ----------------
constexpr int B_  = 8;
constexpr int N_  = 3136;   // H*W
constexpr int C_  = 128;
constexpr int NH_ = 4;
constexpr int D_  = 32;     // C/NH
constexpr int L_  = 9;      // WIN*WIN
constexpr int P_  = 49;     // PH*PW
constexpr int HW_ = 56;     // H == W
constexpr float SCALE_ = 0.08838834764831845f;  // C^-0.5

// ---------------- device scratch (no allocation allowed) ----------------
__device__ __align__(16) float g_kv   [B_*N_*2*C_];   // kv = x @ kv_w.T + b
__device__ __align__(16) float g_srg  [B_*N_*C_];     // gelu(sr(x))
__device__ __align__(16) float g_z    [B_*N_*C_];     // x_local + x_pool
__device__ __align__(16) float g_xacc [B_*N_*C_];     // x_pool per (b,n,c)
__device__ __align__(16) float g_q    [B_*N_*NH_];    // q logits
__device__ __align__(16) float g_ksum [B_*NH_*N_];    // sum_d k
__device__ __align__(16) float g_kpool[B_*NH_*P_];
__device__ __align__(16) float g_vpool[B_*NH_*P_*D_];
__device__ float g_csM[B_*NH_], g_csS[B_*NH_];
__device__ float g_wl [B_*NH_*L_];
__device__ float g_wlf[B_*NH_*L_];
__device__ __align__(16) float g_kvwT [C_*2*C_];      // kv_w transposed (k-major)
__device__ __align__(16) float g_srwT [C_*C_];
__device__ __align__(16) float g_projT[C_*C_];

__device__ __forceinline__ float gelu_exact(float v) {
    return 0.5f * v * (1.0f + erff(v * 0.70710678118654752f));
}

// packed fp32x2 FMA (sm_100a): d = a*b + d  (SASS FFMA2, 2 fp32 per issue)
__device__ __forceinline__ void ffma2(unsigned long long& d,
                                      unsigned long long a,
                                      unsigned long long b) {
    asm("fma.rn.f32x2 %0, %1, %2, %0;" : "+l"(d) : "l"(a), "l"(b));
}
union F4U2 { float4 f; unsigned long long u[2]; };

// ---------------- K0: weight transposes ----------------
__global__ void transpose_k(const float* __restrict__ kvw,
                            const float* __restrict__ srw,
                            const float* __restrict__ pjw)
{
    int i = blockIdx.x * 256 + threadIdx.x;        // grid covers 32768
    int o = i >> 7, k = i & 127;
    if (i < 256 * 128) g_kvwT[k * 256 + o] = kvw[i];
    if (i < 128 * 128) { g_srwT[k * 128 + o] = srw[i]; g_projT[k * 128 + o] = pjw[i]; }
}

// ---------------- register-tiled fp32x2 GEMM template ----------------
// MODE 0: kv = x @ kv_wT (+bias), 256 cols, epilogue also computes q and ksum
// MODE 1: srg = gelu(x @ sr_wT + bias), 128 cols
// MODE 2: out = z @ projT + bias, 128 cols
template<int MODE>
__global__ __launch_bounds__(256) void gemm_k(const float* __restrict__ Xarg,
                                              const float* __restrict__ bias,
                                              float* __restrict__ Outarg,
                                              const float* __restrict__ qw)
{
    constexpr int NCOLS = (MODE == 0) ? 256 : 128;
    constexpr int CT    = NCOLS / 4;        // threads spanning columns (4 cols each)
    constexpr int RPT   = NCOLS / 32;       // rows per thread (8 or 4)

    const float* __restrict__ X  = (MODE == 2) ? g_z : Xarg;
    const float* __restrict__ WT = (MODE == 0) ? g_kvwT : ((MODE == 1) ? g_srwT : g_projT);
    float* __restrict__ Out      = (MODE == 0) ? g_kv : ((MODE == 1) ? g_srg : Outarg);

    // X tile stored as duplicated {x,x} 64-bit pairs -> 1 LDS.64 feeds an FFMA2 pair
    __shared__ __align__(16) unsigned long long xs2[32 * 128];
    int t  = threadIdx.x;
    int cg = t % CT;         // column group (4 consecutive cols)
    int rg = t / CT;         // row group (RPT consecutive rows)
    long row0 = (long)blockIdx.x * 32;

    {
        const float4* X4 = reinterpret_cast<const float4*>(X + row0 * C_);
        #pragma unroll
        for (int i = 0; i < 4; i++) {
            int e = t + i * 256;                  // float4 index within 32x128 tile
            float4 v = X4[e];
            uint4* dst = reinterpret_cast<uint4*>(xs2) + 2 * e;
            dst[0] = make_uint4(__float_as_uint(v.x), __float_as_uint(v.x),
                                __float_as_uint(v.y), __float_as_uint(v.y));
            dst[1] = make_uint4(__float_as_uint(v.z), __float_as_uint(v.z),
                                __float_as_uint(v.w), __float_as_uint(v.w));
        }
    }
    __syncthreads();

    unsigned long long acc2[RPT][2];
    #pragma unroll
    for (int r = 0; r < RPT; r++) { acc2[r][0] = 0ull; acc2[r][1] = 0ull; }

    const float4* W4 = reinterpret_cast<const float4*>(WT) + cg;
    #pragma unroll 4
    for (int k = 0; k < 128; k++) {
        F4U2 w; w.f = __ldg(W4 + k * CT);
        #pragma unroll
        for (int r = 0; r < RPT; r++) {
            unsigned long long xp = xs2[(rg * RPT + r) * 128 + k];  // broadcast LDS.64
            ffma2(acc2[r][0], xp, w.u[0]);
            ffma2(acc2[r][1], xp, w.u[1]);
        }
    }

    float4 bb = reinterpret_cast<const float4*>(bias)[cg];
    #pragma unroll
    for (int r = 0; r < RPT; r++) {
        F4U2 a; a.u[0] = acc2[r][0]; a.u[1] = acc2[r][1];
        float4 v;
        v.x = a.f.x + bb.x; v.y = a.f.y + bb.y;
        v.z = a.f.z + bb.z; v.w = a.f.w + bb.w;
        if (MODE == 1) {
            v.x = gelu_exact(v.x); v.y = gelu_exact(v.y);
            v.z = gelu_exact(v.z); v.w = gelu_exact(v.w);
        }
        reinterpret_cast<float4*>(Out + (row0 + rg * RPT + r) * NCOLS)[cg] = v;
    }

    if (MODE == 0) {
        __syncthreads();   // kv global stores visible within block
        const float* xsf = reinterpret_cast<const float*>(xs2);   // duplicated pairs
        if (t < 128) {
            int r = t >> 2, h = t & 3;
            long grow = row0 + r;
            // q logits (bias/query_embedding cancel in softmax over n)
            float s = 0.f;
            #pragma unroll 8
            for (int k = 0; k < 128; k++)
                s = fmaf(xsf[2 * (r * 128 + k)], qw[h * 128 + k], s);
            g_q[grow * NH_ + h] = s;
            // ksum = sum_d k[head h]
            const float4* kvr = reinterpret_cast<const float4*>(Out + grow * 256 + h * 32);
            float ks = 0.f;
            #pragma unroll
            for (int j = 0; j < 8; j++) { float4 a = kvr[j]; ks += a.x + a.y + a.z + a.w; }
            int b = (int)(grow / N_), n = (int)(grow % N_);
            g_ksum[((long)b * NH_ + h) * N_ + n] = ks;
        }
    }
}

// ---------------- K2b: 8x8 avg-pool + layernorm + kvp -> k_pool / v_pool ----------------
// 256 threads: warp w sums pixel-row w (8 pixels, float4 per lane over channels)
__global__ __launch_bounds__(256) void pool_k(const float* __restrict__ nw,
                                              const float* __restrict__ nb,
                                              const float* __restrict__ kvb)
{
    int b = blockIdx.x / P_, p = blockIdx.x % P_;
    int py = p / 7, px = p % 7;
    int t = threadIdx.x, lane = t & 31, wid = t >> 5;

    __shared__ float4 red[8][32];
    __shared__ float xsn[C_];
    __shared__ float kvs[2 * C_];

    // phase 1: sum 8 pixels of row wid; lane = channel quad
    {
        const float4* src = reinterpret_cast<const float4*>(g_srg);
        long base = (((long)b * N_ + (long)(py * 8 + wid) * HW_ + px * 8) * C_) >> 2;
        float4 a = make_float4(0.f, 0.f, 0.f, 0.f);
        #pragma unroll
        for (int j = 0; j < 8; j++) {
            float4 v = src[base + j * 32 + lane];
            a.x += v.x; a.y += v.y; a.z += v.z; a.w += v.w;
        }
        red[wid][lane] = a;
    }
    __syncthreads();

    // phase 2: reduce 8 rows, layernorm (warp 0 only)
    if (t < 32) {
        float4 s = red[0][t];
        #pragma unroll
        for (int w = 1; w < 8; w++) {
            float4 v = red[w][t];
            s.x += v.x; s.y += v.y; s.z += v.z; s.w += v.w;
        }
        s.x *= (1.f / 64.f); s.y *= (1.f / 64.f); s.z *= (1.f / 64.f); s.w *= (1.f / 64.f);
        float tot = s.x + s.y + s.z + s.w;
        #pragma unroll
        for (int o = 16; o; o >>= 1) tot += __shfl_xor_sync(~0u, tot, o);
        float mu = tot * (1.f / C_);
        float dx = s.x - mu, dy = s.y - mu, dz = s.z - mu, dw = s.w - mu;
        float sq = dx * dx + dy * dy + dz * dz + dw * dw;
        #pragma unroll
        for (int o = 16; o; o >>= 1) sq += __shfl_xor_sync(~0u, sq, o);
        float inv = rsqrtf(sq * (1.f / C_) + 1e-5f);
        float4 w4 = reinterpret_cast<const float4*>(nw)[t];
        float4 b4 = reinterpret_cast<const float4*>(nb)[t];
        float4 xn;
        xn.x = dx * inv * w4.x + b4.x; xn.y = dy * inv * w4.y + b4.y;
        xn.z = dz * inv * w4.z + b4.z; xn.w = dw * inv * w4.w + b4.w;
        reinterpret_cast<float4*>(xsn)[t] = xn;
    }
    __syncthreads();

    // phase 3: kvp matvec — one output per thread
    {
        float a = kvb[t];
        #pragma unroll 8
        for (int k = 0; k < C_; k++) a = fmaf(g_kvwT[k * 256 + t], xsn[k], a);
        kvs[t] = a;
    }
    __syncthreads();

    if (t < NH_) {
        float kp = 0.f;
        #pragma unroll
        for (int d2 = 0; d2 < D_; d2++) kp += kvs[t * D_ + d2];
        g_kpool[(b * NH_ + t) * P_ + p] = kp;
    }
    if (t < C_)
        g_vpool[((b * NH_ + (t >> 5)) * P_ + p) * D_ + (t & 31)] = kvs[C_ + t];
}

// ---------------- K3: context-score softmax stats over n (per b,h) ----------------
__global__ __launch_bounds__(256) void cs_stats_k()
{
    int bh = blockIdx.x;
    int b  = bh >> 2, h = bh & 3;
    int t = threadIdx.x, lane = t & 31, wid = t >> 5;
    __shared__ float sh[8];
    const float* qp = g_q + (long)b * N_ * NH_ + h;

    float m = -INFINITY;
    for (int n = t; n < N_; n += 256) m = fmaxf(m, qp[n * NH_]);
    #pragma unroll
    for (int o = 16; o; o >>= 1) m = fmaxf(m, __shfl_xor_sync(~0u, m, o));
    if (lane == 0) sh[wid] = m;
    __syncthreads();
    float M = sh[0];
    #pragma unroll
    for (int w = 1; w < 8; w++) M = fmaxf(M, sh[w]);
    __syncthreads();

    float s = 0.f;
    for (int n = t; n < N_; n += 256) s += expf(qp[n * NH_] - M);
    #pragma unroll
    for (int o = 16; o; o >>= 1) s += __shfl_xor_sync(~0u, s, o);
    if (lane == 0) sh[wid] = s;
    __syncthreads();
    if (t == 0) {
        float S = 0.f;
        #pragma unroll
        for (int w = 0; w < 8; w++) S += sh[w];
        g_csM[bh] = M;
        g_csS[bh] = 1.f / S;
    }
    if (t < L_) g_wl[bh * L_ + t] = 0.f;   // zero a_local accumulator for K4 atomics
}

// ---------------- K4: per-n 58-way softmax + pool matvec + a_local reduction ----------------
__global__ __launch_bounds__(256) void attn_k(const float* __restrict__ pbp,
                                              const float* __restrict__ pbl)
{
    int bh = blockIdx.y;
    int b  = bh >> 2, h = bh & 3;
    int n0 = blockIdx.x * 64;
    int t = threadIdx.x, lane = t & 31, wid = t >> 5;

    __shared__ float vps[P_ * D_];
    __shared__ float kps[P_];
    __shared__ float asb[8][64];
    __shared__ float wlsh[8][L_];
    __shared__ float msh[2];

    for (int i = t; i < P_ * D_; i += 256) vps[i] = g_vpool[bh * P_ * D_ + i];
    if (t < P_) kps[t] = g_kpool[bh * P_ + t];
    if (t == 0) { msh[0] = g_csM[bh]; msh[1] = g_csS[bh]; }
    __syncthreads();

    float M = msh[0], invS = msh[1];
    const float NEG = -INFINITY;
    float wlacc = 0.f;
    float pbl_l = (lane < L_) ? pbl[h * L_ + lane] : 0.f;

    for (int i = 0; i < 8; i++) {
        int n = n0 + wid * 8 + i;
        float cs  = expf(g_q[((long)b * N_ + n) * NH_ + h] - M) * invS;
        float csS = cs * SCALE_;
        const float* pbpn = pbp + ((long)h * N_ + n) * P_;

        float v0, v1 = NEG;
        if (lane < L_) {
            int y = n / HW_ + lane / 3 - 1, x = n % HW_ + lane % 3 - 1;
            v0 = (y >= 0 && y < HW_ && x >= 0 && x < HW_)
                 ? g_ksum[(long)bh * N_ + y * HW_ + x] * csS + pbl_l : NEG;
        } else {
            int p = lane - L_;
            v0 = csS * kps[p] + pbpn[p];
        }
        if (lane < 26) { int p = lane + 23; v1 = csS * kps[p] + pbpn[p]; }

        float mx = fmaxf(v0, v1);
        #pragma unroll
        for (int o = 16; o; o >>= 1) mx = fmaxf(mx, __shfl_xor_sync(0xffffffffu, mx, o));
        float e0 = expf(v0 - mx);
        float e1 = (lane < 26) ? expf(v1 - mx) : 0.f;
        float se = e0 + e1;
        #pragma unroll
        for (int o = 16; o; o >>= 1) se += __shfl_xor_sync(0xffffffffu, se, o);
        float inv = 1.f / se;
        e0 *= inv; e1 *= inv;

        if (lane < L_) wlacc += e0;                 // sum_n a_local
        asb[wid][lane] = e0;
        if (lane < 26) asb[wid][lane + 32] = e1;
        __syncwarp();

        float acc = 0.f;
        #pragma unroll
        for (int p = 0; p < P_; p++)
            acc = fmaf(asb[wid][L_ + p], vps[p * D_ + lane], acc);
        g_xacc[((long)b * N_ + n) * C_ + h * D_ + lane] = acc;
        __syncwarp();
    }

    if (lane < L_) wlsh[wid][lane] = wlacc;
    __syncthreads();
    if (t < L_) {
        float s = 0.f;
        #pragma unroll
        for (int w = 0; w < 8; w++) s += wlsh[w][t];
        atomicAdd(&g_wl[bh * L_ + t], s);
    }
}

// ---------------- K4b: finalize w_local ----------------
__global__ void wlfinal_k(const float* __restrict__ lt, const float* __restrict__ lb)
{
    int i = blockIdx.x * 256 + threadIdx.x;
    if (i < B_ * NH_ * L_) {
        int l = i % L_, h = (i / L_) & 3;
        g_wlf[i] = lt[h * L_ + l] + (float)N_ * lb[h * L_ + l] + g_wl[i];
    }
}

// ---------------- K5a: z = x_pool + sum_l relu(v[nb(n,l)]) * w_local ----------------
__global__ __launch_bounds__(256) void localmix_k()
{
    long e = (long)blockIdx.x * 256 + threadIdx.x;   // exact: B*N*C elements
    int  c  = (int)(e & (C_ - 1));
    long gr = e >> 7;
    int  b  = (int)(gr / N_), n = (int)(gr % N_);
    int  h  = c >> 5;
    float y = g_xacc[e];
    int yy = n / HW_, xx = n % HW_;
    const float* wf = g_wlf + (b * NH_ + h) * L_;
    #pragma unroll
    for (int l = 0; l < L_; l++) {
        int py = yy + l / 3 - 1, px = xx + l % 3 - 1;
        if (py >= 0 && py < HW_ && px >= 0 && px < HW_) {
            float v = g_kv[((long)b * N_ + py * HW_ + px) * (2 * C_) + C_ + c];
            y = fmaf(fmaxf(v, 0.f), wf[l], y);
        }
    }
    g_z[e] = y;
}

// ---------------- launch ----------------
extern "C" void kernel_launch(void* const* d_in, const int* in_sizes, int n_in,
                              void* d_out, int out_size)
{
    const float* x    = (const float*)d_in[0];
    const float* q_w  = (const float*)d_in[1];
    // d_in[2] q_b, d_in[3] query_embedding: cancel in softmax over n — unused
    const float* kv_w = (const float*)d_in[4];
    const float* kv_b = (const float*)d_in[5];
    const float* sr_w = (const float*)d_in[6];
    const float* sr_b = (const float*)d_in[7];
    const float* nw   = (const float*)d_in[8];
    const float* nb   = (const float*)d_in[9];
    const float* pbp  = (const float*)d_in[10];
    const float* pbl  = (const float*)d_in[11];
    const float* lt   = (const float*)d_in[12];
    const float* lb   = (const float*)d_in[13];
    const float* pjw  = (const float*)d_in[14];
    const float* pjb  = (const float*)d_in[15];
    float* out = (float*)d_out;

    transpose_k<<<128, 256>>>(kv_w, sr_w, pjw);
    gemm_k<0><<<784, 256>>>(x, kv_b, nullptr, q_w);      // kv + q + ksum
    gemm_k<1><<<784, 256>>>(x, sr_b, nullptr, nullptr);  // gelu(sr(x))
    pool_k<<<B_ * P_, 256>>>(nw, nb, kv_b);              // pool + LN + kvp
    cs_stats_k<<<B_ * NH_, 256>>>();                     // context softmax stats
    dim3 g4(49, B_ * NH_);
    attn_k<<<g4, 256>>>(pbp, pbl);                       // 58-way softmax + x_pool
    wlfinal_k<<<2, 256>>>(lt, lb);
    localmix_k<<<12544, 256>>>();                        // z = x_pool + local
    gemm_k<2><<<784, 256>>>(nullptr, pjb, out, nullptr); // projection
}

// round 4
// speedup vs baseline: 1.1397x; 1.1397x over previous
#include <cuda_runtime.h>
#include <math.h>

// ---------------- problem constants ----------------
constexpr int B_  = 8;
constexpr int N_  = 3136;   // H*W
constexpr int C_  = 128;
constexpr int NH_ = 4;
constexpr int D_  = 32;     // C/NH
constexpr int L_  = 9;      // WIN*WIN
constexpr int P_  = 49;     // PH*PW
constexpr int HW_ = 56;     // H == W
constexpr float SCALE_ = 0.08838834764831845f;  // C^-0.5

// ---------------- device scratch (no allocation allowed) ----------------
__device__ __align__(16) float g_rv   [B_*N_*C_];     // relu(v + bias)        (12.8 MB)
__device__ __align__(16) float g_srg  [B_*N_*C_];     // gelu(sr(x))
__device__ __align__(16) float g_z    [B_*N_*C_];     // x_local + x_pool
__device__ __align__(16) float g_xacc [B_*N_*C_];     // x_pool per (b,n,c)
__device__ __align__(16) float g_q    [B_*N_*NH_];    // q logits
__device__ __align__(16) float g_ksum [B_*NH_*N_];    // sum_d k
__device__ __align__(16) float g_kpool[B_*NH_*P_];
__device__ __align__(16) float g_vpool[B_*NH_*P_*D_];
__device__ float g_csM[B_*NH_], g_csS[B_*NH_];
__device__ float g_wl [B_*NH_*L_];
__device__ float g_wlf[B_*NH_*L_];
__device__ __align__(16) float g_vwT  [C_*C_];        // v-half of kv_w, k-major
__device__ __align__(16) float g_kswT [NH_*C_];       // per-head d-summed k weights [h][k]
__device__ float g_ksb[NH_];                          // per-head summed k bias
__device__ __align__(16) float g_srwT [C_*C_];
__device__ __align__(16) float g_projT[C_*C_];

__device__ __forceinline__ float gelu_exact(float v) {
    return 0.5f * v * (1.0f + erff(v * 0.70710678118654752f));
}

// ---------------- K0: weight transposes + k-weight folding ----------------
__global__ void transpose_k(const float* __restrict__ kvw,
                            const float* __restrict__ kvb,
                            const float* __restrict__ srw,
                            const float* __restrict__ pjw)
{
    int i = blockIdx.x * 256 + threadIdx.x;        // grid covers 16384
    int o = i >> 7, k = i & 127;
    if (i < 128 * 128) {
        g_vwT  [k * 128 + o] = kvw[(128 + o) * 128 + k];   // v rows 128..255
        g_srwT [k * 128 + o] = srw[i];
        g_projT[k * 128 + o] = pjw[i];
    }
    if (i < NH_ * 128) {                          // folded k weights: h = o&3? no:
        int h = i >> 7;                           // h in 0..3, k = i&127
        float s = 0.f;
        #pragma unroll
        for (int j = 0; j < D_; j++) s += kvw[(h * D_ + j) * 128 + k];
        g_kswT[h * 128 + k] = s;
    }
    if (i < NH_) {
        float s = 0.f;
        #pragma unroll
        for (int j = 0; j < D_; j++) s += kvb[i * D_ + j];
        g_ksb[i] = s;
    }
}

// ---------------- register-tiled fp32 GEMM (128 cols) ----------------
// MODE 0: rv = relu(x @ vwT + vbias); epilogue computes q and ksum from x tile
// MODE 1: srg = gelu(x @ srwT + bias)
// MODE 2: out = z @ projT + bias
template<int MODE>
__global__ __launch_bounds__(256) void gemm_k(const float* __restrict__ Xarg,
                                              const float* __restrict__ bias,
                                              float* __restrict__ Outarg,
                                              const float* __restrict__ qw)
{
    const float* __restrict__ X  = (MODE == 2) ? g_z : Xarg;
    const float* __restrict__ WT = (MODE == 0) ? g_vwT : ((MODE == 1) ? g_srwT : g_projT);
    float* __restrict__ Out      = (MODE == 0) ? g_rv : ((MODE == 1) ? g_srg : Outarg);

    __shared__ __align__(16) float xs[32 * 128];
    int t  = threadIdx.x;
    int cg = t & 31;         // column group (4 consecutive cols)
    int rg = t >> 5;         // row group (4 consecutive rows)
    long row0 = (long)blockIdx.x * 32;

    {
        const float4* X4 = reinterpret_cast<const float4*>(X + row0 * C_);
        float4* xs4 = reinterpret_cast<float4*>(xs);
        #pragma unroll
        for (int i = 0; i < 4; i++) xs4[t + i * 256] = X4[t + i * 256];
    }
    __syncthreads();

    float acc[4][4];
    #pragma unroll
    for (int r = 0; r < 4; r++) { acc[r][0] = acc[r][1] = acc[r][2] = acc[r][3] = 0.f; }

    const float4* W4 = reinterpret_cast<const float4*>(WT) + cg;
    #pragma unroll 4
    for (int k = 0; k < 128; k++) {
        float4 w = __ldg(W4 + k * 32);
        #pragma unroll
        for (int r = 0; r < 4; r++) {
            float xv = xs[(rg * 4 + r) * 128 + k];   // broadcast LDS
            acc[r][0] = fmaf(xv, w.x, acc[r][0]);
            acc[r][1] = fmaf(xv, w.y, acc[r][1]);
            acc[r][2] = fmaf(xv, w.z, acc[r][2]);
            acc[r][3] = fmaf(xv, w.w, acc[r][3]);
        }
    }

    float4 bb = reinterpret_cast<const float4*>(bias)[cg];
    #pragma unroll
    for (int r = 0; r < 4; r++) {
        float4 v;
        v.x = acc[r][0] + bb.x; v.y = acc[r][1] + bb.y;
        v.z = acc[r][2] + bb.z; v.w = acc[r][3] + bb.w;
        if (MODE == 0) {
            v.x = fmaxf(v.x, 0.f); v.y = fmaxf(v.y, 0.f);
            v.z = fmaxf(v.z, 0.f); v.w = fmaxf(v.w, 0.f);
        }
        if (MODE == 1) {
            v.x = gelu_exact(v.x); v.y = gelu_exact(v.y);
            v.z = gelu_exact(v.z); v.w = gelu_exact(v.w);
        }
        reinterpret_cast<float4*>(Out + (row0 + rg * 4 + r) * C_)[cg] = v;
    }

    if (MODE == 0) {
        // q + folded ksum: 32 rows x 8 outputs = 256 threads, one dot each
        int r = t >> 3, u = t & 7;                  // u<4: q head u; u>=4: ksum head u-4
        const float* wv = (u < 4) ? (qw + u * 128) : (g_kswT + (u - 4) * 128);
        float s = (u < 4) ? 0.f : g_ksb[u - 4];
        const float* xr = xs + r * 128;
        #pragma unroll 8
        for (int k = 0; k < 128; k++) s = fmaf(xr[k], wv[k], s);
        long grow = row0 + r;
        if (u < 4) {
            g_q[grow * NH_ + u] = s;
        } else {
            int b = (int)(grow / N_), n = (int)(grow % N_);
            g_ksum[((long)b * NH_ + (u - 4)) * N_ + n] = s;
        }
    }
}

// ---------------- K2b: 8x8 avg-pool + layernorm + kvp -> k_pool / v_pool ----------------
__global__ __launch_bounds__(256) void pool_k(const float* __restrict__ nw,
                                              const float* __restrict__ nb,
                                              const float* __restrict__ kvb)
{
    int b = blockIdx.x / P_, p = blockIdx.x % P_;
    int py = p / 7, px = p % 7;
    int t = threadIdx.x, lane = t & 31, wid = t >> 5;

    __shared__ float4 red[8][32];
    __shared__ float xsn[C_];

    // phase 1: warp w sums pixel-row w (8 pixels, float4 per lane over channels)
    {
        const float4* src = reinterpret_cast<const float4*>(g_srg);
        long base = (((long)b * N_ + (long)(py * 8 + wid) * HW_ + px * 8) * C_) >> 2;
        float4 a = make_float4(0.f, 0.f, 0.f, 0.f);
        #pragma unroll
        for (int j = 0; j < 8; j++) {
            float4 v = src[base + j * 32 + lane];
            a.x += v.x; a.y += v.y; a.z += v.z; a.w += v.w;
        }
        red[wid][lane] = a;
    }
    __syncthreads();

    // phase 2: reduce 8 rows, layernorm (warp 0 only)
    if (t < 32) {
        float4 s = red[0][t];
        #pragma unroll
        for (int w = 1; w < 8; w++) {
            float4 v = red[w][t];
            s.x += v.x; s.y += v.y; s.z += v.z; s.w += v.w;
        }
        s.x *= (1.f / 64.f); s.y *= (1.f / 64.f); s.z *= (1.f / 64.f); s.w *= (1.f / 64.f);
        float tot = s.x + s.y + s.z + s.w;
        #pragma unroll
        for (int o = 16; o; o >>= 1) tot += __shfl_xor_sync(~0u, tot, o);
        float mu = tot * (1.f / C_);
        float dx = s.x - mu, dy = s.y - mu, dz = s.z - mu, dw = s.w - mu;
        float sq = dx * dx + dy * dy + dz * dz + dw * dw;
        #pragma unroll
        for (int o = 16; o; o >>= 1) sq += __shfl_xor_sync(~0u, sq, o);
        float inv = rsqrtf(sq * (1.f / C_) + 1e-5f);
        float4 w4 = reinterpret_cast<const float4*>(nw)[t];
        float4 b4 = reinterpret_cast<const float4*>(nb)[t];
        float4 xn;
        xn.x = dx * inv * w4.x + b4.x; xn.y = dy * inv * w4.y + b4.y;
        xn.z = dz * inv * w4.z + b4.z; xn.w = dw * inv * w4.w + b4.w;
        reinterpret_cast<float4*>(xsn)[t] = xn;
    }
    __syncthreads();

    // phase 3: v_pool matvec (threads 0..127) + folded k_pool (threads 128..131)
    if (t < C_) {
        float a = kvb[C_ + t];
        #pragma unroll 8
        for (int k = 0; k < C_; k++) a = fmaf(g_vwT[k * 128 + t], xsn[k], a);
        g_vpool[((b * NH_ + (t >> 5)) * P_ + p) * D_ + (t & 31)] = a;
    } else if (t < C_ + NH_) {
        int h = t - C_;
        float a = g_ksb[h];
        #pragma unroll 8
        for (int k = 0; k < C_; k++) a = fmaf(g_kswT[h * 128 + k], xsn[k], a);
        g_kpool[(b * NH_ + h) * P_ + p] = a;
    }
}

// ---------------- K3: context-score softmax stats over n (per b,h) ----------------
__global__ __launch_bounds__(256) void cs_stats_k()
{
    int bh = blockIdx.x;
    int b  = bh >> 2, h = bh & 3;
    int t = threadIdx.x, lane = t & 31, wid = t >> 5;
    __shared__ float sh[8];
    const float* qp = g_q + (long)b * N_ * NH_ + h;

    float m = -INFINITY;
    for (int n = t; n < N_; n += 256) m = fmaxf(m, qp[n * NH_]);
    #pragma unroll
    for (int o = 16; o; o >>= 1) m = fmaxf(m, __shfl_xor_sync(~0u, m, o));
    if (lane == 0) sh[wid] = m;
    __syncthreads();
    float M = sh[0];
    #pragma unroll
    for (int w = 1; w < 8; w++) M = fmaxf(M, sh[w]);
    __syncthreads();

    float s = 0.f;
    for (int n = t; n < N_; n += 256) s += expf(qp[n * NH_] - M);
    #pragma unroll
    for (int o = 16; o; o >>= 1) s += __shfl_xor_sync(~0u, s, o);
    if (lane == 0) sh[wid] = s;
    __syncthreads();
    if (t == 0) {
        float S = 0.f;
        #pragma unroll
        for (int w = 0; w < 8; w++) S += sh[w];
        g_csM[bh] = M;
        g_csS[bh] = 1.f / S;
    }
    if (t < L_) g_wl[bh * L_ + t] = 0.f;   // zero a_local accumulator for K4 atomics
}

// ---------------- K4: per-n 58-way softmax + pool matvec + a_local reduction ----------------
__global__ __launch_bounds__(256) void attn_k(const float* __restrict__ pbp,
                                              const float* __restrict__ pbl)
{
    int bh = blockIdx.y;
    int b  = bh >> 2, h = bh & 3;
    int n0 = blockIdx.x * 64;
    int t = threadIdx.x, lane = t & 31, wid = t >> 5;

    __shared__ float vps[P_ * D_];
    __shared__ float kps[P_];
    __shared__ float asb[8][64];
    __shared__ float wlsh[8][L_];
    __shared__ float msh[2];

    for (int i = t; i < P_ * D_; i += 256) vps[i] = g_vpool[bh * P_ * D_ + i];
    if (t < P_) kps[t] = g_kpool[bh * P_ + t];
    if (t == 0) { msh[0] = g_csM[bh]; msh[1] = g_csS[bh]; }
    __syncthreads();

    float M = msh[0], invS = msh[1];
    const float NEG = -INFINITY;
    float wlacc = 0.f;
    float pbl_l = (lane < L_) ? pbl[h * L_ + lane] : 0.f;

    for (int i = 0; i < 8; i++) {
        int n = n0 + wid * 8 + i;
        float cs  = expf(g_q[((long)b * N_ + n) * NH_ + h] - M) * invS;
        float csS = cs * SCALE_;
        const float* pbpn = pbp + ((long)h * N_ + n) * P_;

        float v0, v1 = NEG;
        if (lane < L_) {
            int y = n / HW_ + lane / 3 - 1, x = n % HW_ + lane % 3 - 1;
            v0 = (y >= 0 && y < HW_ && x >= 0 && x < HW_)
                 ? g_ksum[(long)bh * N_ + y * HW_ + x] * csS + pbl_l : NEG;
        } else {
            int p = lane - L_;
            v0 = csS * kps[p] + pbpn[p];
        }
        if (lane < 26) { int p = lane + 23; v1 = csS * kps[p] + pbpn[p]; }

        float mx = fmaxf(v0, v1);
        #pragma unroll
        for (int o = 16; o; o >>= 1) mx = fmaxf(mx, __shfl_xor_sync(0xffffffffu, mx, o));
        float e0 = expf(v0 - mx);
        float e1 = (lane < 26) ? expf(v1 - mx) : 0.f;
        float se = e0 + e1;
        #pragma unroll
        for (int o = 16; o; o >>= 1) se += __shfl_xor_sync(0xffffffffu, se, o);
        float inv = 1.f / se;
        e0 *= inv; e1 *= inv;

        if (lane < L_) wlacc += e0;                 // sum_n a_local
        asb[wid][lane] = e0;
        if (lane < 26) asb[wid][lane + 32] = e1;
        __syncwarp();

        float acc = 0.f;
        #pragma unroll
        for (int p = 0; p < P_; p++)
            acc = fmaf(asb[wid][L_ + p], vps[p * D_ + lane], acc);
        g_xacc[((long)b * N_ + n) * C_ + h * D_ + lane] = acc;
        __syncwarp();
    }

    if (lane < L_) wlsh[wid][lane] = wlacc;
    __syncthreads();
    if (t < L_) {
        float s = 0.f;
        #pragma unroll
        for (int w = 0; w < 8; w++) s += wlsh[w][t];
        atomicAdd(&g_wl[bh * L_ + t], s);
    }
}

// ---------------- K4b: finalize w_local ----------------
__global__ void wlfinal_k(const float* __restrict__ lt, const float* __restrict__ lb)
{
    int i = blockIdx.x * 256 + threadIdx.x;
    if (i < B_ * NH_ * L_) {
        int l = i % L_, h = (i / L_) & 3;
        g_wlf[i] = lt[h * L_ + l] + (float)N_ * lb[h * L_ + l] + g_wl[i];
    }
}

// ---------------- K5a: z = x_pool + sum_l rv[nb(n,l)] * w_local ----------------
__global__ __launch_bounds__(256) void localmix_k()
{
    long e = (long)blockIdx.x * 256 + threadIdx.x;   // exact: B*N*C elements
    int  c  = (int)(e & (C_ - 1));
    long gr = e >> 7;
    int  b  = (int)(gr / N_), n = (int)(gr % N_);
    int  h  = c >> 5;
    float y = g_xacc[e];
    int yy = n / HW_, xx = n % HW_;
    const float* wf = g_wlf + (b * NH_ + h) * L_;
    #pragma unroll
    for (int l = 0; l < L_; l++) {
        int py = yy + l / 3 - 1, px = xx + l % 3 - 1;
        if (py >= 0 && py < HW_ && px >= 0 && px < HW_) {
            float v = g_rv[((long)b * N_ + py * HW_ + px) * C_ + c];
            y = fmaf(v, wf[l], y);
        }
    }
    g_z[e] = y;
}

// ---------------- launch ----------------
extern "C" void kernel_launch(void* const* d_in, const int* in_sizes, int n_in,
                              void* d_out, int out_size)
{
    const float* x    = (const float*)d_in[0];
    const float* q_w  = (const float*)d_in[1];
    // d_in[2] q_b, d_in[3] query_embedding: cancel in softmax over n — unused
    const float* kv_w = (const float*)d_in[4];
    const float* kv_b = (const float*)d_in[5];
    const float* sr_w = (const float*)d_in[6];
    const float* sr_b = (const float*)d_in[7];
    const float* nw   = (const float*)d_in[8];
    const float* nb   = (const float*)d_in[9];
    const float* pbp  = (const float*)d_in[10];
    const float* pbl  = (const float*)d_in[11];
    const float* lt   = (const float*)d_in[12];
    const float* lb   = (const float*)d_in[13];
    const float* pjw  = (const float*)d_in[14];
    const float* pjb  = (const float*)d_in[15];
    float* out = (float*)d_out;

    transpose_k<<<64, 256>>>(kv_w, kv_b, sr_w, pjw);
    gemm_k<0><<<784, 256>>>(x, kv_b + C_, nullptr, q_w); // relu(v) + q + ksum
    gemm_k<1><<<784, 256>>>(x, sr_b, nullptr, nullptr);  // gelu(sr(x))
    pool_k<<<B_ * P_, 256>>>(nw, nb, kv_b);              // pool + LN + kvp (folded k)
    cs_stats_k<<<B_ * NH_, 256>>>();                     // context softmax stats
    dim3 g4(49, B_ * NH_);
    attn_k<<<g4, 256>>>(pbp, pbl);                       // 58-way softmax + x_pool
    wlfinal_k<<<2, 256>>>(lt, lb);
    localmix_k<<<12544, 256>>>();                        // z = x_pool + local
    gemm_k<2><<<784, 256>>>(nullptr, pjb, out, nullptr); // projection
}

// round 5
// speedup vs baseline: 1.9084x; 1.6745x over previous
#include <cuda_runtime.h>
#include <math.h>

// ---------------- problem constants ----------------
constexpr int B_  = 8;
constexpr int N_  = 3136;   // H*W
constexpr int C_  = 128;
constexpr int NH_ = 4;
constexpr int D_  = 32;     // C/NH
constexpr int L_  = 9;      // WIN*WIN
constexpr int P_  = 49;     // PH*PW
constexpr int HW_ = 56;     // H == W
constexpr float SCALE_ = 0.08838834764831845f;  // C^-0.5

constexpr int WS_  = 144;   // padded weight column stride (tf32 ext matrices)
constexpr int XS_  = 132;   // padded x-tile row stride
constexpr int SMEM_GEMM = (64 * XS_ + 128 * WS_) * 4;   // 107520 B

// ---------------- device scratch (no allocation allowed) ----------------
__device__ __align__(16) float g_rv   [B_*N_*C_];     // relu(v + bias)
__device__ __align__(16) float g_srg  [B_*N_*C_];     // gelu(sr(x))
__device__ __align__(16) float g_z    [B_*N_*C_];     // x_local + x_pool
__device__ __align__(16) float g_xacc [B_*N_*C_];     // x_pool per (b,n,c)
__device__ __align__(16) float g_q    [B_*N_*NH_];    // q logits
__device__ __align__(16) float g_ksum [B_*NH_*N_];    // sum_d k
__device__ __align__(16) float g_kpool[B_*NH_*P_];
__device__ __align__(16) float g_vpool[B_*NH_*P_*D_];
__device__ float g_csM[B_*NH_], g_csS[B_*NH_];
__device__ float g_wl [B_*NH_*L_];
__device__ float g_wlf[B_*NH_*L_];
__device__ float g_ksb[NH_];                          // per-head summed k bias
__device__ __align__(16) float g_vwT  [C_*C_];        // v weights k-major (fp32, pool)
__device__ __align__(16) float g_kswT [NH_*C_];       // folded k weights (fp32, pool)
__device__ __align__(16) unsigned g_w0[C_*WS_];       // tf32 ext: v | qw | ksw | 0
__device__ __align__(16) unsigned g_w1[C_*WS_];       // tf32 ext: sr | 0
__device__ __align__(16) unsigned g_w2[C_*WS_];       // tf32 ext: proj | 0

__device__ __forceinline__ float gelu_exact(float v) {
    return 0.5f * v * (1.0f + erff(v * 0.70710678118654752f));
}
__device__ __forceinline__ unsigned tf32_of(float f) {
    unsigned u; asm("cvt.rna.tf32.f32 %0, %1;" : "=r"(u) : "f"(f)); return u;
}
__device__ __forceinline__ void mma_tf32(float* c, const unsigned* a,
                                         unsigned b0, unsigned b1) {
    asm volatile("mma.sync.aligned.m16n8k8.row.col.f32.tf32.tf32.f32 "
        "{%0,%1,%2,%3}, {%4,%5,%6,%7}, {%8,%9}, {%0,%1,%2,%3};"
        : "+f"(c[0]), "+f"(c[1]), "+f"(c[2]), "+f"(c[3])
        : "r"(a[0]), "r"(a[1]), "r"(a[2]), "r"(a[3]), "r"(b0), "r"(b1));
}

// ---------------- K0: weight prep (tf32 ext matrices + fp32 pool weights) ----------------
__global__ void transpose_k(const float* __restrict__ kvw,
                            const float* __restrict__ kvb,
                            const float* __restrict__ qw,
                            const float* __restrict__ srw,
                            const float* __restrict__ pjw)
{
    int i = blockIdx.x * 256 + threadIdx.x;      // grid covers 128*144 = 18432
    if (i >= C_ * WS_) return;
    int k = i / WS_, c = i % WS_;
    float v0 = 0.f, v1 = 0.f, v2 = 0.f;
    if (c < 128) {
        v0 = kvw[(128 + c) * 128 + k];           // v rows of kv_w
        v1 = srw[c * 128 + k];
        v2 = pjw[c * 128 + k];
        g_vwT[k * 128 + c] = v0;                 // fp32 copy for pool_k
    } else if (c < 132) {
        v0 = qw[(c - 128) * 128 + k];
    } else if (c < 136) {
        float s = 0.f;
        #pragma unroll
        for (int j = 0; j < D_; j++) s += kvw[((c - 132) * D_ + j) * 128 + k];
        v0 = s;
        g_kswT[(c - 132) * 128 + k] = s;         // fp32 copy for pool_k
    }
    g_w0[i] = tf32_of(v0);
    g_w1[i] = tf32_of(v1);
    g_w2[i] = tf32_of(v2);
    if (i < NH_) {
        float s = 0.f;
        #pragma unroll
        for (int j = 0; j < D_; j++) s += kvb[i * D_ + j];
        g_ksb[i] = s;
    }
}

// ---------------- tf32 mma GEMM: 64 rows x 128 cols per block, 8 warps ----------------
// MODE 0: rv = relu(x @ vwT + vb); extra cols 128-135 -> q, ksum
// MODE 1: srg = gelu(x @ srwT + b)
// MODE 2: out = z @ projT + b
template<int MODE>
__global__ __launch_bounds__(256) void gemm_k(const float* __restrict__ Xarg,
                                              const float* __restrict__ bias,
                                              float* __restrict__ Outarg)
{
    const float* __restrict__ X  = (MODE == 2) ? g_z : Xarg;
    const unsigned* __restrict__ Wg = (MODE == 0) ? g_w0 : ((MODE == 1) ? g_w1 : g_w2);
    float* __restrict__ Out      = (MODE == 0) ? g_rv : ((MODE == 1) ? g_srg : Outarg);

    extern __shared__ unsigned smem_u[];
    unsigned* xs = smem_u;                  // [64][132] tf32
    unsigned* ws = smem_u + 64 * XS_;       // [128][144] tf32

    const int t = threadIdx.x;
    const int lane = t & 31, w = t >> 5;
    const int g4 = lane >> 2, tg = lane & 3;
    const int wm = w >> 2, wn = w & 3;      // 2 x 4 warp grid
    const int rbase = wm * 32, cbase = wn * 32;
    const long row0 = (long)blockIdx.x * 64;

    // fill x tile (fp32 -> tf32), stride 132 keeps float4 alignment (132 % 4 == 0)
    {
        const float4* X4 = reinterpret_cast<const float4*>(X + row0 * C_);
        #pragma unroll
        for (int i = 0; i < 8; i++) {
            int idx = t + i * 256;          // 2048 float4 = 64 rows x 32
            int r = idx >> 5, c4 = idx & 31;
            float4 v = X4[idx];
            uint4 u = make_uint4(tf32_of(v.x), tf32_of(v.y), tf32_of(v.z), tf32_of(v.w));
            *reinterpret_cast<uint4*>(xs + r * XS_ + c4 * 4) = u;
        }
    }
    // fill weight tile: straight copy (padding already in global layout)
    {
        const uint4* W4 = reinterpret_cast<const uint4*>(Wg);
        uint4* ws4 = reinterpret_cast<uint4*>(ws);
        #pragma unroll
        for (int i = 0; i < 18; i++) ws4[t + i * 256] = W4[t + i * 256];
    }
    __syncthreads();

    float acc[2][4][4];
    #pragma unroll
    for (int mt = 0; mt < 2; mt++)
        #pragma unroll
        for (int nt = 0; nt < 4; nt++)
            #pragma unroll
            for (int j = 0; j < 4; j++) acc[mt][nt][j] = 0.f;
    float accE[2][4];
    #pragma unroll
    for (int mt = 0; mt < 2; mt++)
        #pragma unroll
        for (int j = 0; j < 4; j++) accE[mt][j] = 0.f;

    #pragma unroll
    for (int kk = 0; kk < 16; kk++) {
        unsigned a[2][4];
        const unsigned* xa = xs + (rbase + g4) * XS_ + kk * 8 + tg;
        #pragma unroll
        for (int mt = 0; mt < 2; mt++) {
            const unsigned* x2 = xa + mt * 16 * XS_;
            a[mt][0] = x2[0];
            a[mt][1] = x2[8 * XS_];
            a[mt][2] = x2[4];
            a[mt][3] = x2[8 * XS_ + 4];
        }
        const unsigned* wb = ws + (kk * 8 + tg) * WS_ + g4;
        #pragma unroll
        for (int nt = 0; nt < 4; nt++) {
            unsigned b0 = wb[cbase + nt * 8];
            unsigned b1 = wb[4 * WS_ + cbase + nt * 8];
            mma_tf32(acc[0][nt], a[0], b0, b1);
            mma_tf32(acc[1][nt], a[1], b0, b1);
        }
        if (MODE == 0 && wn == 0) {
            unsigned b0 = wb[128];
            unsigned b1 = wb[4 * WS_ + 128];
            mma_tf32(accE[0], a[0], b0, b1);
            mma_tf32(accE[1], a[1], b0, b1);
        }
    }

    // ---- main epilogue: bias + activation, float2 stores ----
    #pragma unroll
    for (int mt = 0; mt < 2; mt++) {
        #pragma unroll
        for (int nt = 0; nt < 4; nt++) {
            int col = cbase + nt * 8 + 2 * tg;
            float b0 = bias[col], b1 = bias[col + 1];
            #pragma unroll
            for (int half = 0; half < 2; half++) {
                long rl = row0 + rbase + mt * 16 + g4 + half * 8;
                float v0 = acc[mt][nt][half * 2 + 0] + b0;
                float v1 = acc[mt][nt][half * 2 + 1] + b1;
                if (MODE == 0) { v0 = fmaxf(v0, 0.f); v1 = fmaxf(v1, 0.f); }
                if (MODE == 1) { v0 = gelu_exact(v0); v1 = gelu_exact(v1); }
                *reinterpret_cast<float2*>(Out + rl * C_ + col) = make_float2(v0, v1);
            }
        }
    }

    // ---- extra-column epilogue: q + ksum (warps with wn == 0) ----
    if (MODE == 0 && wn == 0) {
        #pragma unroll
        for (int mt = 0; mt < 2; mt++) {
            #pragma unroll
            for (int half = 0; half < 2; half++) {
                long grow = row0 + rbase + mt * 16 + g4 + half * 8;
                int b = (int)(grow / N_), n = (int)(grow % N_);
                #pragma unroll
                for (int j = 0; j < 2; j++) {
                    int col = 128 + 2 * tg + j;
                    float v = accE[mt][half * 2 + j];
                    if (col < 132) {
                        g_q[grow * NH_ + (col - 128)] = v;
                    } else {
                        int h = col - 132;
                        g_ksum[((long)b * NH_ + h) * N_ + n] = v + g_ksb[h];
                    }
                }
            }
        }
    }
}

// ---------------- K2b: 8x8 avg-pool + layernorm + kvp -> k_pool / v_pool ----------------
__global__ __launch_bounds__(256) void pool_k(const float* __restrict__ nw,
                                              const float* __restrict__ nb,
                                              const float* __restrict__ kvb)
{
    int b = blockIdx.x / P_, p = blockIdx.x % P_;
    int py = p / 7, px = p % 7;
    int t = threadIdx.x, lane = t & 31, wid = t >> 5;

    __shared__ float4 red[8][32];
    __shared__ float xsn[C_];

    {
        const float4* src = reinterpret_cast<const float4*>(g_srg);
        long base = (((long)b * N_ + (long)(py * 8 + wid) * HW_ + px * 8) * C_) >> 2;
        float4 a = make_float4(0.f, 0.f, 0.f, 0.f);
        #pragma unroll
        for (int j = 0; j < 8; j++) {
            float4 v = src[base + j * 32 + lane];
            a.x += v.x; a.y += v.y; a.z += v.z; a.w += v.w;
        }
        red[wid][lane] = a;
    }
    __syncthreads();

    if (t < 32) {
        float4 s = red[0][t];
        #pragma unroll
        for (int w = 1; w < 8; w++) {
            float4 v = red[w][t];
            s.x += v.x; s.y += v.y; s.z += v.z; s.w += v.w;
        }
        s.x *= (1.f / 64.f); s.y *= (1.f / 64.f); s.z *= (1.f / 64.f); s.w *= (1.f / 64.f);
        float tot = s.x + s.y + s.z + s.w;
        #pragma unroll
        for (int o = 16; o; o >>= 1) tot += __shfl_xor_sync(~0u, tot, o);
        float mu = tot * (1.f / C_);
        float dx = s.x - mu, dy = s.y - mu, dz = s.z - mu, dw = s.w - mu;
        float sq = dx * dx + dy * dy + dz * dz + dw * dw;
        #pragma unroll
        for (int o = 16; o; o >>= 1) sq += __shfl_xor_sync(~0u, sq, o);
        float inv = rsqrtf(sq * (1.f / C_) + 1e-5f);
        float4 w4 = reinterpret_cast<const float4*>(nw)[t];
        float4 b4 = reinterpret_cast<const float4*>(nb)[t];
        float4 xn;
        xn.x = dx * inv * w4.x + b4.x; xn.y = dy * inv * w4.y + b4.y;
        xn.z = dz * inv * w4.z + b4.z; xn.w = dw * inv * w4.w + b4.w;
        reinterpret_cast<float4*>(xsn)[t] = xn;
    }
    __syncthreads();

    if (t < C_) {
        float a = kvb[C_ + t];
        #pragma unroll 8
        for (int k = 0; k < C_; k++) a = fmaf(g_vwT[k * 128 + t], xsn[k], a);
        g_vpool[((b * NH_ + (t >> 5)) * P_ + p) * D_ + (t & 31)] = a;
    } else if (t < C_ + NH_) {
        int h = t - C_;
        float a = g_ksb[h];
        #pragma unroll 8
        for (int k = 0; k < C_; k++) a = fmaf(g_kswT[h * 128 + k], xsn[k], a);
        g_kpool[(b * NH_ + h) * P_ + p] = a;
    }
}

// ---------------- K3: context-score softmax stats over n (per b,h) ----------------
__global__ __launch_bounds__(256) void cs_stats_k()
{
    int bh = blockIdx.x;
    int b  = bh >> 2, h = bh & 3;
    int t = threadIdx.x, lane = t & 31, wid = t >> 5;
    __shared__ float sh[8];
    const float* qp = g_q + (long)b * N_ * NH_ + h;

    float m = -INFINITY;
    for (int n = t; n < N_; n += 256) m = fmaxf(m, qp[n * NH_]);
    #pragma unroll
    for (int o = 16; o; o >>= 1) m = fmaxf(m, __shfl_xor_sync(~0u, m, o));
    if (lane == 0) sh[wid] = m;
    __syncthreads();
    float M = sh[0];
    #pragma unroll
    for (int w = 1; w < 8; w++) M = fmaxf(M, sh[w]);
    __syncthreads();

    float s = 0.f;
    for (int n = t; n < N_; n += 256) s += expf(qp[n * NH_] - M);
    #pragma unroll
    for (int o = 16; o; o >>= 1) s += __shfl_xor_sync(~0u, s, o);
    if (lane == 0) sh[wid] = s;
    __syncthreads();
    if (t == 0) {
        float S = 0.f;
        #pragma unroll
        for (int w = 0; w < 8; w++) S += sh[w];
        g_csM[bh] = M;
        g_csS[bh] = 1.f / S;
    }
    if (t < L_) g_wl[bh * L_ + t] = 0.f;
}

// ---------------- K4: per-n 58-way softmax + pool matvec + a_local reduction ----------------
__global__ __launch_bounds__(256) void attn_k(const float* __restrict__ pbp,
                                              const float* __restrict__ pbl)
{
    int bh = blockIdx.y;
    int b  = bh >> 2, h = bh & 3;
    int n0 = blockIdx.x * 64;
    int t = threadIdx.x, lane = t & 31, wid = t >> 5;

    __shared__ float vps[P_ * D_];
    __shared__ float kps[P_];
    __shared__ float asb[8][64];
    __shared__ float wlsh[8][L_];
    __shared__ float msh[2];

    for (int i = t; i < P_ * D_; i += 256) vps[i] = g_vpool[bh * P_ * D_ + i];
    if (t < P_) kps[t] = g_kpool[bh * P_ + t];
    if (t == 0) { msh[0] = g_csM[bh]; msh[1] = g_csS[bh]; }
    __syncthreads();

    float M = msh[0], invS = msh[1];
    const float NEG = -INFINITY;
    float wlacc = 0.f;
    float pbl_l = (lane < L_) ? pbl[h * L_ + lane] : 0.f;

    for (int i = 0; i < 8; i++) {
        int n = n0 + wid * 8 + i;
        float cs  = expf(g_q[((long)b * N_ + n) * NH_ + h] - M) * invS;
        float csS = cs * SCALE_;
        const float* pbpn = pbp + ((long)h * N_ + n) * P_;

        float v0, v1 = NEG;
        if (lane < L_) {
            int y = n / HW_ + lane / 3 - 1, x = n % HW_ + lane % 3 - 1;
            v0 = (y >= 0 && y < HW_ && x >= 0 && x < HW_)
                 ? g_ksum[(long)bh * N_ + y * HW_ + x] * csS + pbl_l : NEG;
        } else {
            int p = lane - L_;
            v0 = csS * kps[p] + pbpn[p];
        }
        if (lane < 26) { int p = lane + 23; v1 = csS * kps[p] + pbpn[p]; }

        float mx = fmaxf(v0, v1);
        #pragma unroll
        for (int o = 16; o; o >>= 1) mx = fmaxf(mx, __shfl_xor_sync(0xffffffffu, mx, o));
        float e0 = expf(v0 - mx);
        float e1 = (lane < 26) ? expf(v1 - mx) : 0.f;
        float se = e0 + e1;
        #pragma unroll
        for (int o = 16; o; o >>= 1) se += __shfl_xor_sync(0xffffffffu, se, o);
        float inv = 1.f / se;
        e0 *= inv; e1 *= inv;

        if (lane < L_) wlacc += e0;
        asb[wid][lane] = e0;
        if (lane < 26) asb[wid][lane + 32] = e1;
        __syncwarp();

        float acc = 0.f;
        #pragma unroll
        for (int p = 0; p < P_; p++)
            acc = fmaf(asb[wid][L_ + p], vps[p * D_ + lane], acc);
        g_xacc[((long)b * N_ + n) * C_ + h * D_ + lane] = acc;
        __syncwarp();
    }

    if (lane < L_) wlsh[wid][lane] = wlacc;
    __syncthreads();
    if (t < L_) {
        float s = 0.f;
        #pragma unroll
        for (int w = 0; w < 8; w++) s += wlsh[w][t];
        atomicAdd(&g_wl[bh * L_ + t], s);
    }
}

// ---------------- K4b: finalize w_local ----------------
__global__ void wlfinal_k(const float* __restrict__ lt, const float* __restrict__ lb)
{
    int i = blockIdx.x * 256 + threadIdx.x;
    if (i < B_ * NH_ * L_) {
        int l = i % L_, h = (i / L_) & 3;
        g_wlf[i] = lt[h * L_ + l] + (float)N_ * lb[h * L_ + l] + g_wl[i];
    }
}

// ---------------- K5a: z = x_pool + sum_l rv[nb(n,l)] * w_local ----------------
__global__ __launch_bounds__(256) void localmix_k()
{
    long e = (long)blockIdx.x * 256 + threadIdx.x;
    int  c  = (int)(e & (C_ - 1));
    long gr = e >> 7;
    int  b  = (int)(gr / N_), n = (int)(gr % N_);
    int  h  = c >> 5;
    float y = g_xacc[e];
    int yy = n / HW_, xx = n % HW_;
    const float* wf = g_wlf + (b * NH_ + h) * L_;
    #pragma unroll
    for (int l = 0; l < L_; l++) {
        int py = yy + l / 3 - 1, px = xx + l % 3 - 1;
        if (py >= 0 && py < HW_ && px >= 0 && px < HW_) {
            float v = g_rv[((long)b * N_ + py * HW_ + px) * C_ + c];
            y = fmaf(v, wf[l], y);
        }
    }
    g_z[e] = y;
}

// ---------------- launch ----------------
extern "C" void kernel_launch(void* const* d_in, const int* in_sizes, int n_in,
                              void* d_out, int out_size)
{
    const float* x    = (const float*)d_in[0];
    const float* q_w  = (const float*)d_in[1];
    const float* kv_w = (const float*)d_in[4];
    const float* kv_b = (const float*)d_in[5];
    const float* sr_w = (const float*)d_in[6];
    const float* sr_b = (const float*)d_in[7];
    const float* nw   = (const float*)d_in[8];
    const float* nb   = (const float*)d_in[9];
    const float* pbp  = (const float*)d_in[10];
    const float* pbl  = (const float*)d_in[11];
    const float* lt   = (const float*)d_in[12];
    const float* lb   = (const float*)d_in[13];
    const float* pjw  = (const float*)d_in[14];
    const float* pjb  = (const float*)d_in[15];
    float* out = (float*)d_out;

    static bool attr_set = false;
    if (!attr_set) {
        cudaFuncSetAttribute(gemm_k<0>, cudaFuncAttributeMaxDynamicSharedMemorySize, SMEM_GEMM);
        cudaFuncSetAttribute(gemm_k<1>, cudaFuncAttributeMaxDynamicSharedMemorySize, SMEM_GEMM);
        cudaFuncSetAttribute(gemm_k<2>, cudaFuncAttributeMaxDynamicSharedMemorySize, SMEM_GEMM);
        attr_set = true;
    }

    transpose_k<<<72, 256>>>(kv_w, kv_b, q_w, sr_w, pjw);
    gemm_k<0><<<392, 256, SMEM_GEMM>>>(x, kv_b + C_, nullptr);   // relu(v) + q + ksum
    gemm_k<1><<<392, 256, SMEM_GEMM>>>(x, sr_b, nullptr);        // gelu(sr(x))
    pool_k<<<B_ * P_, 256>>>(nw, nb, kv_b);                      // pool + LN + kvp
    cs_stats_k<<<B_ * NH_, 256>>>();                             // context softmax stats
    dim3 g4(49, B_ * NH_);
    attn_k<<<g4, 256>>>(pbp, pbl);                               // 58-way softmax + x_pool
    wlfinal_k<<<2, 256>>>(lt, lb);
    localmix_k<<<12544, 256>>>();                                // z = x_pool + local
    gemm_k<2><<<392, 256, SMEM_GEMM>>>(nullptr, pjb, out);       // projection
}

// round 6
// speedup vs baseline: 2.0610x; 1.0800x over previous
#include <cuda_runtime.h>
#include <math.h>

// ---------------- problem constants ----------------
constexpr int B_  = 8;
constexpr int N_  = 3136;   // H*W
constexpr int C_  = 128;
constexpr int NH_ = 4;
constexpr int D_  = 32;     // C/NH
constexpr int L_  = 9;      // WIN*WIN
constexpr int P_  = 49;     // PH*PW
constexpr int HW_ = 56;     // H == W
constexpr float SCALE_ = 0.08838834764831845f;  // C^-0.5

constexpr int WS_  = 144;   // padded weight column stride (tf32 ext matrices)
constexpr int XS_  = 132;   // padded x-tile row stride
constexpr int SMEM_GEMM = (64 * XS_ + 128 * WS_) * 4;   // 107520 B

// ---------------- device scratch (no allocation allowed) ----------------
__device__ __align__(16) float g_rv   [B_*N_*C_];     // relu(v + bias)
__device__ __align__(16) float g_z    [B_*N_*C_];     // x_local + x_pool
__device__ __align__(16) float g_xacc [B_*N_*C_];     // x_pool per (b,n,c)
__device__ __align__(16) float g_q    [B_*N_*NH_];    // q logits
__device__ __align__(16) float g_ksum [B_*NH_*N_];    // sum_d k
__device__ __align__(16) float g_xp   [B_*P_*C_];     // pooled sums (pre /64)
__device__ __align__(16) float g_kpool[B_*NH_*P_];
__device__ __align__(16) float g_vpool[B_*NH_*P_*D_];
__device__ float g_csM[B_*NH_], g_csS[B_*NH_];
__device__ float g_wl [B_*NH_*L_];
__device__ float g_wlf[B_*NH_*L_];
__device__ float g_ksb[NH_];                          // per-head summed k bias
__device__ __align__(16) float g_vwT  [C_*C_];        // v weights k-major (fp32, pool)
__device__ __align__(16) float g_kswT [NH_*C_];       // folded k weights (fp32, pool)
__device__ __align__(16) unsigned g_w0[C_*WS_];       // tf32 ext: v | qw | ksw | 0
__device__ __align__(16) unsigned g_w1[C_*WS_];       // tf32 ext: sr | 0
__device__ __align__(16) unsigned g_w2[C_*WS_];       // tf32 ext: proj | 0

__device__ __forceinline__ float gelu_exact(float v) {
    return 0.5f * v * (1.0f + erff(v * 0.70710678118654752f));
}
__device__ __forceinline__ unsigned tf32_of(float f) {
    unsigned u; asm("cvt.rna.tf32.f32 %0, %1;" : "=r"(u) : "f"(f)); return u;
}
__device__ __forceinline__ void mma_tf32(float* c, const unsigned* a,
                                         unsigned b0, unsigned b1) {
    asm volatile("mma.sync.aligned.m16n8k8.row.col.f32.tf32.tf32.f32 "
        "{%0,%1,%2,%3}, {%4,%5,%6,%7}, {%8,%9}, {%0,%1,%2,%3};"
        : "+f"(c[0]), "+f"(c[1]), "+f"(c[2]), "+f"(c[3])
        : "r"(a[0]), "r"(a[1]), "r"(a[2]), "r"(a[3]), "r"(b0), "r"(b1));
}

// ---------------- K0: weight prep + zero g_xp ----------------
__global__ void transpose_k(const float* __restrict__ kvw,
                            const float* __restrict__ kvb,
                            const float* __restrict__ qw,
                            const float* __restrict__ srw,
                            const float* __restrict__ pjw)
{
    int i = blockIdx.x * 256 + threadIdx.x;      // grid covers 128*144 = 18432
    for (int j = i; j < B_ * P_ * C_; j += 72 * 256) g_xp[j] = 0.f;
    if (i >= C_ * WS_) return;
    int k = i / WS_, c = i % WS_;
    float v0 = 0.f, v1 = 0.f, v2 = 0.f;
    if (c < 128) {
        v0 = kvw[(128 + c) * 128 + k];           // v rows of kv_w
        v1 = srw[c * 128 + k];
        v2 = pjw[c * 128 + k];
        g_vwT[k * 128 + c] = v0;                 // fp32 copy for pool2_k
    } else if (c < 132) {
        v0 = qw[(c - 128) * 128 + k];
    } else if (c < 136) {
        float s = 0.f;
        #pragma unroll
        for (int j = 0; j < D_; j++) s += kvw[((c - 132) * D_ + j) * 128 + k];
        v0 = s;
        g_kswT[(c - 132) * 128 + k] = s;         // fp32 copy for pool2_k
    }
    g_w0[i] = tf32_of(v0);
    g_w1[i] = tf32_of(v1);
    g_w2[i] = tf32_of(v2);
    if (i < NH_) {
        float s = 0.f;
        #pragma unroll
        for (int j = 0; j < D_; j++) s += kvb[i * D_ + j];
        g_ksb[i] = s;
    }
}

// ---------------- tf32 mma GEMM: 64 rows x 128 cols per block, 8 warps ----------------
// MODE 0: rv = relu(x @ vwT + vb); extra cols 128-135 -> q, ksum
// MODE 1: gelu(x @ srwT + b) -> pooled sums into g_xp (atomicAdd), no dense store
// MODE 2: out = z @ projT + b
template<int MODE>
__global__ __launch_bounds__(256) void gemm_k(const float* __restrict__ Xarg,
                                              const float* __restrict__ bias,
                                              float* __restrict__ Outarg)
{
    const float* __restrict__ X  = (MODE == 2) ? g_z : Xarg;
    const unsigned* __restrict__ Wg = (MODE == 0) ? g_w0 : ((MODE == 1) ? g_w1 : g_w2);
    float* __restrict__ Out      = (MODE == 0) ? g_rv : Outarg;

    extern __shared__ unsigned smem_u[];
    unsigned* xs = smem_u;                  // [64][132] tf32
    unsigned* ws = smem_u + 64 * XS_;       // [128][144] tf32
    __shared__ int bkt[64];

    const int t = threadIdx.x;
    const int lane = t & 31, w = t >> 5;
    const int g4 = lane >> 2, tg = lane & 3;
    const int wm = w >> 2, wn = w & 3;      // 2 x 4 warp grid
    const int rbase = wm * 32, cbase = wn * 32;
    const long row0 = (long)blockIdx.x * 64;

    // fill x tile (fp32 -> tf32)
    {
        const float4* X4 = reinterpret_cast<const float4*>(X + row0 * C_);
        #pragma unroll
        for (int i = 0; i < 8; i++) {
            int idx = t + i * 256;
            int r = idx >> 5, c4 = idx & 31;
            float4 v = X4[idx];
            uint4 u = make_uint4(tf32_of(v.x), tf32_of(v.y), tf32_of(v.z), tf32_of(v.w));
            *reinterpret_cast<uint4*>(xs + r * XS_ + c4 * 4) = u;
        }
    }
    // fill weight tile
    {
        const uint4* W4 = reinterpret_cast<const uint4*>(Wg);
        uint4* ws4 = reinterpret_cast<uint4*>(ws);
        #pragma unroll
        for (int i = 0; i < 18; i++) ws4[t + i * 256] = W4[t + i * 256];
    }
    __syncthreads();

    float acc[2][4][4];
    #pragma unroll
    for (int mt = 0; mt < 2; mt++)
        #pragma unroll
        for (int nt = 0; nt < 4; nt++)
            #pragma unroll
            for (int j = 0; j < 4; j++) acc[mt][nt][j] = 0.f;
    float accE[2][4];
    #pragma unroll
    for (int mt = 0; mt < 2; mt++)
        #pragma unroll
        for (int j = 0; j < 4; j++) accE[mt][j] = 0.f;

    #pragma unroll
    for (int kk = 0; kk < 16; kk++) {
        unsigned a[2][4];
        const unsigned* xa = xs + (rbase + g4) * XS_ + kk * 8 + tg;
        #pragma unroll
        for (int mt = 0; mt < 2; mt++) {
            const unsigned* x2 = xa + mt * 16 * XS_;
            a[mt][0] = x2[0];
            a[mt][1] = x2[8 * XS_];
            a[mt][2] = x2[4];
            a[mt][3] = x2[8 * XS_ + 4];
        }
        const unsigned* wb = ws + (kk * 8 + tg) * WS_ + g4;
        #pragma unroll
        for (int nt = 0; nt < 4; nt++) {
            unsigned b0 = wb[cbase + nt * 8];
            unsigned b1 = wb[4 * WS_ + cbase + nt * 8];
            mma_tf32(acc[0][nt], a[0], b0, b1);
            mma_tf32(acc[1][nt], a[1], b0, b1);
        }
        if (MODE == 0 && wn == 0) {
            unsigned b0 = wb[128];
            unsigned b1 = wb[4 * WS_ + 128];
            mma_tf32(accE[0], a[0], b0, b1);
            mma_tf32(accE[1], a[1], b0, b1);
        }
    }

    if (MODE == 1) {
        // gelu tile -> smem (reuse ws), then bucketed pool reduction -> g_xp
        __syncthreads();                        // all warps done reading ws
        float* gt = reinterpret_cast<float*>(ws);   // [64][128]
        #pragma unroll
        for (int mt = 0; mt < 2; mt++) {
            #pragma unroll
            for (int nt = 0; nt < 4; nt++) {
                int col = cbase + nt * 8 + 2 * tg;
                float b0 = bias[col], b1 = bias[col + 1];
                #pragma unroll
                for (int half = 0; half < 2; half++) {
                    int r = rbase + mt * 16 + g4 + half * 8;
                    float v0 = gelu_exact(acc[mt][nt][half * 2 + 0] + b0);
                    float v1 = gelu_exact(acc[mt][nt][half * 2 + 1] + b1);
                    *reinterpret_cast<float2*>(gt + r * 128 + col) = make_float2(v0, v1);
                }
            }
        }
        int b = (int)(row0 / N_), n0 = (int)(row0 % N_);
        if (t < 64) {
            int n = n0 + t, y = n / HW_, x = n - y * HW_;
            bkt[t] = (y >> 3) * 7 + (x >> 3);
        }
        __syncthreads();
        int col = t & 127, half = t >> 7;
        int r0 = half * 32;
        float a = 0.f;
        int cur = bkt[r0];
        #pragma unroll 4
        for (int r = r0; r < r0 + 32; r++) {
            int bk = bkt[r];
            if (bk != cur) {
                atomicAdd(&g_xp[((long)b * P_ + cur) * C_ + col], a);
                a = 0.f; cur = bk;
            }
            a += gt[r * 128 + col];
        }
        atomicAdd(&g_xp[((long)b * P_ + cur) * C_ + col], a);
        return;
    }

    // ---- main epilogue (MODE 0 / 2): bias + activation, float2 stores ----
    #pragma unroll
    for (int mt = 0; mt < 2; mt++) {
        #pragma unroll
        for (int nt = 0; nt < 4; nt++) {
            int col = cbase + nt * 8 + 2 * tg;
            float b0 = bias[col], b1 = bias[col + 1];
            #pragma unroll
            for (int half = 0; half < 2; half++) {
                long rl = row0 + rbase + mt * 16 + g4 + half * 8;
                float v0 = acc[mt][nt][half * 2 + 0] + b0;
                float v1 = acc[mt][nt][half * 2 + 1] + b1;
                if (MODE == 0) { v0 = fmaxf(v0, 0.f); v1 = fmaxf(v1, 0.f); }
                *reinterpret_cast<float2*>(Out + rl * C_ + col) = make_float2(v0, v1);
            }
        }
    }

    // ---- extra-column epilogue: q + ksum (warps with wn == 0) ----
    if (MODE == 0 && wn == 0) {
        #pragma unroll
        for (int mt = 0; mt < 2; mt++) {
            #pragma unroll
            for (int half = 0; half < 2; half++) {
                long grow = row0 + rbase + mt * 16 + g4 + half * 8;
                int b = (int)(grow / N_), n = (int)(grow % N_);
                #pragma unroll
                for (int j = 0; j < 2; j++) {
                    int col = 128 + 2 * tg + j;
                    float v = accE[mt][half * 2 + j];
                    if (col < 132) {
                        g_q[grow * NH_ + (col - 128)] = v;
                    } else {
                        int h = col - 132;
                        g_ksum[((long)b * NH_ + h) * N_ + n] = v + g_ksb[h];
                    }
                }
            }
        }
    }
}

// ---------------- K2b: layernorm + kvp on pooled rows -> k_pool / v_pool ----------------
__global__ __launch_bounds__(256) void pool2_k(const float* __restrict__ nw,
                                               const float* __restrict__ nb,
                                               const float* __restrict__ kvb)
{
    int b = blockIdx.x / P_, p = blockIdx.x % P_;
    int t = threadIdx.x, lane = t & 31, wid = t >> 5;

    __shared__ float xsn[C_];
    __shared__ float sh[4];

    float s = 0.f;
    if (t < C_) s = g_xp[((long)b * P_ + p) * C_ + t] * (1.f / 64.f);

    // block LN over 128 channels (threads 0..127 hold one channel each)
    float v = (t < C_) ? s : 0.f;
    #pragma unroll
    for (int o = 16; o; o >>= 1) v += __shfl_xor_sync(~0u, v, o);
    if (lane == 0 && wid < 4) sh[wid] = v;
    __syncthreads();
    float mu = (sh[0] + sh[1] + sh[2] + sh[3]) * (1.f / C_);
    float d  = s - mu;
    __syncthreads();
    v = (t < C_) ? d * d : 0.f;
    #pragma unroll
    for (int o = 16; o; o >>= 1) v += __shfl_xor_sync(~0u, v, o);
    if (lane == 0 && wid < 4) sh[wid] = v;
    __syncthreads();
    float var = (sh[0] + sh[1] + sh[2] + sh[3]) * (1.f / C_);
    if (t < C_) xsn[t] = d * rsqrtf(var + 1e-5f) * nw[t] + nb[t];
    __syncthreads();

    if (t < C_) {
        float a = kvb[C_ + t];
        #pragma unroll 8
        for (int k = 0; k < C_; k++) a = fmaf(g_vwT[k * 128 + t], xsn[k], a);
        g_vpool[((b * NH_ + (t >> 5)) * P_ + p) * D_ + (t & 31)] = a;
    } else if (t < C_ + NH_) {
        int h = t - C_;
        float a = g_ksb[h];
        #pragma unroll 8
        for (int k = 0; k < C_; k++) a = fmaf(g_kswT[h * 128 + k], xsn[k], a);
        g_kpool[(b * NH_ + h) * P_ + p] = a;
    }
}

// ---------------- K3: context-score softmax stats over n (per b,h) ----------------
__global__ __launch_bounds__(256) void cs_stats_k()
{
    int bh = blockIdx.x;
    int b  = bh >> 2, h = bh & 3;
    int t = threadIdx.x, lane = t & 31, wid = t >> 5;
    __shared__ float sh[8];
    const float* qp = g_q + (long)b * N_ * NH_ + h;

    float m = -INFINITY;
    for (int n = t; n < N_; n += 256) m = fmaxf(m, qp[n * NH_]);
    #pragma unroll
    for (int o = 16; o; o >>= 1) m = fmaxf(m, __shfl_xor_sync(~0u, m, o));
    if (lane == 0) sh[wid] = m;
    __syncthreads();
    float M = sh[0];
    #pragma unroll
    for (int w = 1; w < 8; w++) M = fmaxf(M, sh[w]);
    __syncthreads();

    float s = 0.f;
    for (int n = t; n < N_; n += 256) s += __expf(qp[n * NH_] - M);
    #pragma unroll
    for (int o = 16; o; o >>= 1) s += __shfl_xor_sync(~0u, s, o);
    if (lane == 0) sh[wid] = s;
    __syncthreads();
    if (t == 0) {
        float S = 0.f;
        #pragma unroll
        for (int w = 0; w < 8; w++) S += sh[w];
        g_csM[bh] = M;
        g_csS[bh] = 1.f / S;
    }
    if (t < L_) g_wl[bh * L_ + t] = 0.f;
}

// ---------------- K4: per-n 58-way softmax + pool matvec + a_local reduction ----------------
__global__ __launch_bounds__(256) void attn_k(const float* __restrict__ pbp,
                                              const float* __restrict__ pbl)
{
    int bh = blockIdx.y;
    int b  = bh >> 2, h = bh & 3;
    int n0 = blockIdx.x * 64;
    int t = threadIdx.x, lane = t & 31, wid = t >> 5;

    __shared__ float vps[P_ * D_];
    __shared__ float kps[P_];
    __shared__ float asb[8][64];
    __shared__ float wlsh[8][L_];
    __shared__ float msh[2];

    for (int i = t; i < P_ * D_; i += 256) vps[i] = g_vpool[bh * P_ * D_ + i];
    if (t < P_) kps[t] = g_kpool[bh * P_ + t];
    if (t == 0) { msh[0] = g_csM[bh]; msh[1] = g_csS[bh]; }
    __syncthreads();

    float M = msh[0], invS = msh[1];
    const float NEG = -INFINITY;
    float wlacc = 0.f;
    float pbl_l = (lane < L_) ? pbl[h * L_ + lane] : 0.f;

    for (int i = 0; i < 8; i++) {
        int n = n0 + wid * 8 + i;
        float cs  = __expf(g_q[((long)b * N_ + n) * NH_ + h] - M) * invS;
        float csS = cs * SCALE_;
        const float* pbpn = pbp + ((long)h * N_ + n) * P_;

        float v0, v1 = NEG;
        if (lane < L_) {
            int y = n / HW_ + lane / 3 - 1, x = n % HW_ + lane % 3 - 1;
            v0 = (y >= 0 && y < HW_ && x >= 0 && x < HW_)
                 ? g_ksum[(long)bh * N_ + y * HW_ + x] * csS + pbl_l : NEG;
        } else {
            int p = lane - L_;
            v0 = csS * kps[p] + pbpn[p];
        }
        if (lane < 26) { int p = lane + 23; v1 = csS * kps[p] + pbpn[p]; }

        float mx = fmaxf(v0, v1);
        #pragma unroll
        for (int o = 16; o; o >>= 1) mx = fmaxf(mx, __shfl_xor_sync(0xffffffffu, mx, o));
        float e0 = __expf(v0 - mx);
        float e1 = (lane < 26) ? __expf(v1 - mx) : 0.f;
        float se = e0 + e1;
        #pragma unroll
        for (int o = 16; o; o >>= 1) se += __shfl_xor_sync(0xffffffffu, se, o);
        float inv = 1.f / se;
        e0 *= inv; e1 *= inv;

        if (lane < L_) wlacc += e0;
        asb[wid][lane] = e0;
        if (lane < 26) asb[wid][lane + 32] = e1;
        __syncwarp();

        float acc = 0.f;
        #pragma unroll
        for (int p = 0; p < P_; p++)
            acc = fmaf(asb[wid][L_ + p], vps[p * D_ + lane], acc);
        g_xacc[((long)b * N_ + n) * C_ + h * D_ + lane] = acc;
        __syncwarp();
    }

    if (lane < L_) wlsh[wid][lane] = wlacc;
    __syncthreads();
    if (t < L_) {
        float s = 0.f;
        #pragma unroll
        for (int w = 0; w < 8; w++) s += wlsh[w][t];
        atomicAdd(&g_wl[bh * L_ + t], s);
    }
}

// ---------------- K4b: finalize w_local ----------------
__global__ void wlfinal_k(const float* __restrict__ lt, const float* __restrict__ lb)
{
    int i = blockIdx.x * 256 + threadIdx.x;
    if (i < B_ * NH_ * L_) {
        int l = i % L_, h = (i / L_) & 3;
        g_wlf[i] = lt[h * L_ + l] + (float)N_ * lb[h * L_ + l] + g_wl[i];
    }
}

// ---------------- K5a: z = x_pool + sum_l rv[nb(n,l)] * w_local (float4) ----------------
__global__ __launch_bounds__(256) void localmix_k()
{
    int idx = blockIdx.x * 256 + threadIdx.x;        // B*N*32 channel-quads
    int c4 = idx & 31;                               // channel quad (warp-varying)
    int gr = idx >> 5;                               // b*N + n   (warp-uniform)
    int b  = gr / N_, n = gr - b * N_;
    int h  = c4 >> 3;
    int yy = n / HW_, xx = n - yy * HW_;

    const float4* xacc4 = reinterpret_cast<const float4*>(g_xacc);
    const float4* rv4   = reinterpret_cast<const float4*>(g_rv);
    float4 y = xacc4[(long)gr * 32 + c4];
    const float* wf = g_wlf + (b * NH_ + h) * L_;

    #pragma unroll
    for (int l = 0; l < L_; l++) {
        int py = yy + l / 3 - 1, px = xx + l % 3 - 1;
        if (py >= 0 && py < HW_ && px >= 0 && px < HW_) {
            float4 v = rv4[((long)b * N_ + py * HW_ + px) * 32 + c4];
            float wl = wf[l];
            y.x = fmaf(v.x, wl, y.x); y.y = fmaf(v.y, wl, y.y);
            y.z = fmaf(v.z, wl, y.z); y.w = fmaf(v.w, wl, y.w);
        }
    }
    reinterpret_cast<float4*>(g_z)[(long)gr * 32 + c4] = y;
}

// ---------------- launch ----------------
extern "C" void kernel_launch(void* const* d_in, const int* in_sizes, int n_in,
                              void* d_out, int out_size)
{
    const float* x    = (const float*)d_in[0];
    const float* q_w  = (const float*)d_in[1];
    const float* kv_w = (const float*)d_in[4];
    const float* kv_b = (const float*)d_in[5];
    const float* sr_w = (const float*)d_in[6];
    const float* sr_b = (const float*)d_in[7];
    const float* nw   = (const float*)d_in[8];
    const float* nb   = (const float*)d_in[9];
    const float* pbp  = (const float*)d_in[10];
    const float* pbl  = (const float*)d_in[11];
    const float* lt   = (const float*)d_in[12];
    const float* lb   = (const float*)d_in[13];
    const float* pjw  = (const float*)d_in[14];
    const float* pjb  = (const float*)d_in[15];
    float* out = (float*)d_out;

    static bool attr_set = false;
    if (!attr_set) {
        cudaFuncSetAttribute(gemm_k<0>, cudaFuncAttributeMaxDynamicSharedMemorySize, SMEM_GEMM);
        cudaFuncSetAttribute(gemm_k<1>, cudaFuncAttributeMaxDynamicSharedMemorySize, SMEM_GEMM);
        cudaFuncSetAttribute(gemm_k<2>, cudaFuncAttributeMaxDynamicSharedMemorySize, SMEM_GEMM);
        attr_set = true;
    }

    transpose_k<<<72, 256>>>(kv_w, kv_b, q_w, sr_w, pjw);        // weights + zero g_xp
    gemm_k<0><<<392, 256, SMEM_GEMM>>>(x, kv_b + C_, nullptr);   // relu(v) + q + ksum
    gemm_k<1><<<392, 256, SMEM_GEMM>>>(x, sr_b, nullptr);        // gelu(sr) + fused pool
    pool2_k<<<B_ * P_, 256>>>(nw, nb, kv_b);                     // LN + kvp on pooled rows
    cs_stats_k<<<B_ * NH_, 256>>>();                             // context softmax stats
    dim3 g4(49, B_ * NH_);
    attn_k<<<g4, 256>>>(pbp, pbl);                               // 58-way softmax + x_pool
    wlfinal_k<<<2, 256>>>(lt, lb);
    localmix_k<<<3136, 256>>>();                                 // z = x_pool + local
    gemm_k<2><<<392, 256, SMEM_GEMM>>>(nullptr, pjb, out);       // projection
}